// round 15
// baseline (speedup 1.0000x reference)
#include <cuda_runtime.h>
#include <cuda_fp16.h>
#include <cstdint>

#define MSA_S 256
#define NRES  384
#define C     32
#define CZ    128
#define IC    (NRES * C)          // 12288
#define NPAIR (NRES * NRES)       // 147456
#define CD    (C * C)             // 1024

// ------------------------------ scratch ----------------------------------
__device__ __half g_ah[MSA_S * IC];                // LN(m)@W1  [s][ic] fp16
__device__ __half g_bh[MSA_S * IC];                // LN(m)@W2  [s][ic] fp16
__device__ __half g_w3h[CD * CZ];                  // [cd][e] fp16
__device__ __half g_o[(size_t)NPAIR * CD];         // 302 MB fp16

// --------------------------- helpers -------------------------------------
__device__ __forceinline__ uint32_t smem_u32(const void* p) {
    uint32_t a;
    asm("{ .reg .u64 t; cvta.to.shared.u64 t, %1; cvt.u32.u64 %0, t; }"
        : "=r"(a) : "l"(p));
    return a;
}
__device__ __forceinline__ void cp16(uint32_t saddr, const void* g) {
    asm volatile("cp.async.cg.shared.global [%0], [%1], 16;"
                 :: "r"(saddr), "l"(g) : "memory");
}
__device__ __forceinline__ void ldsm4(uint32_t* r, uint32_t addr) {
    asm volatile("ldmatrix.sync.aligned.m8n8.x4.shared.b16 {%0,%1,%2,%3}, [%4];"
                 : "=r"(r[0]), "=r"(r[1]), "=r"(r[2]), "=r"(r[3]) : "r"(addr));
}
__device__ __forceinline__ void ldsm4t(uint32_t* r, uint32_t addr) {
    asm volatile("ldmatrix.sync.aligned.m8n8.x4.trans.shared.b16 {%0,%1,%2,%3}, [%4];"
                 : "=r"(r[0]), "=r"(r[1]), "=r"(r[2]), "=r"(r[3]) : "r"(addr));
}
__device__ __forceinline__ void mma16816(float* d, const uint32_t* a,
                                         const uint32_t* b) {
    asm volatile(
        "mma.sync.aligned.m16n8k16.row.col.f32.f16.f16.f32 "
        "{%0,%1,%2,%3}, {%4,%5,%6,%7}, {%8,%9}, {%0,%1,%2,%3};"
        : "+f"(d[0]), "+f"(d[1]), "+f"(d[2]), "+f"(d[3])
        : "r"(a[0]), "r"(a[1]), "r"(a[2]), "r"(a[3]), "r"(b[0]), "r"(b[1]));
}
// packed fp32x2
__device__ __forceinline__ unsigned long long pack2(float x, float y) {
    unsigned long long r;
    asm("mov.b64 %0, {%1, %2};" : "=l"(r) : "f"(x), "f"(y));
    return r;
}
__device__ __forceinline__ void unpack2(unsigned long long v, float& x, float& y) {
    asm("mov.b64 {%0, %1}, %2;" : "=f"(x), "=f"(y) : "l"(v));
}
__device__ __forceinline__ void ffma2(unsigned long long& d,
                                      unsigned long long a,
                                      unsigned long long b) {
    asm("fma.rn.f32x2 %0, %1, %2, %0;" : "+l"(d) : "l"(a), "l"(b));
}

#define PITCHT  272               // [k][128] tile pitch: 256B data + 16B pad
// gemm1: A panel resident [256k][128m]; B chunks 64k x 128 double-buffered
#define G1_AB    (256 * PITCHT)             // 69632
#define G1_BT    (64 * PITCHT)              // 17408
#define G1_SMEM  (G1_AB + 2 * G1_BT)        // 104448
#define TPC      32                         // gemm1 tiles per CTA (same bi row)
// gemm2: A [128m][64k] pitch 144; B [64k][128e] pitch 272; 3-stage, persistent
#define PITCHA2  144
#define TBA2     (128 * PITCHA2)            // 18432
#define TBB2     G1_BT                      // 17408
#define G2_STG   (TBA2 + TBB2)              // 35840
#define G2_SMEM  (3 * G2_STG)               // 107520
#define TP2      4                          // gemm2 m-tiles per CTA

// -------------------------------------------------------------------------
// Kernel 1: fused LayerNorm + dual projection -> fp16 [s][ic].
// 4 rows per warp iteration; 128-thread CTAs. Projection uses packed
// fp32x2 FFMA with (aA,aB) fused accumulators and pack2(W1,W2) weights.
// Blocks < 128 also convert their slice of W3 to fp16.
// -------------------------------------------------------------------------
#define LNR 4
__global__ void __launch_bounds__(128)
ln_proj_kernel(const float* __restrict__ m,
               const float* __restrict__ gamma,
               const float* __restrict__ beta,
               const float* __restrict__ W1,
               const float* __restrict__ W2,
               const float* __restrict__ W3) {
    const int lane = threadIdx.x & 31, wid = threadIdx.x >> 5;

    if (blockIdx.x < 128) {          // W3 convert: 128 blocks x 1024 floats
        int i = blockIdx.x * 1024 + threadIdx.x * 8;
        float4 v0 = *(const float4*)(W3 + i);
        float4 v1 = *(const float4*)(W3 + i + 4);
        *(__half2*)(g_w3h + i)     = __floats2half2_rn(v0.x, v0.y);
        *(__half2*)(g_w3h + i + 2) = __floats2half2_rn(v0.z, v0.w);
        *(__half2*)(g_w3h + i + 4) = __floats2half2_rn(v1.x, v1.y);
        *(__half2*)(g_w3h + i + 6) = __floats2half2_rn(v1.z, v1.w);
    }

    unsigned long long wp[32];       // (W1[c][lane], W2[c][lane]) packed
    #pragma unroll
    for (int c = 0; c < 32; c++)
        wp[c] = pack2(W1[c * C + lane], W2[c * C + lane]);
    const float ga = gamma[lane], be = beta[lane];
    const int stride = gridDim.x * 4 * LNR;         // rows per sweep

    for (int r0 = (blockIdx.x * 4 + wid) * LNR; r0 < MSA_S * NRES; r0 += stride) {
        float v[LNR], s[LNR], q[LNR], mn[LNR];
        #pragma unroll
        for (int j = 0; j < LNR; j++)
            v[j] = m[(size_t)(r0 + j) * C + lane];
        #pragma unroll
        for (int j = 0; j < LNR; j++) s[j] = v[j];
        #pragma unroll
        for (int o = 16; o; o >>= 1)
            #pragma unroll
            for (int j = 0; j < LNR; j++)
                s[j] += __shfl_xor_sync(0xffffffffu, s[j], o);
        #pragma unroll
        for (int j = 0; j < LNR; j++) {
            float mu = s[j] * (1.0f / C);
            v[j] -= mu;
            q[j] = v[j] * v[j];
        }
        #pragma unroll
        for (int o = 16; o; o >>= 1)
            #pragma unroll
            for (int j = 0; j < LNR; j++)
                q[j] += __shfl_xor_sync(0xffffffffu, q[j], o);
        #pragma unroll
        for (int j = 0; j < LNR; j++) {
            float rstd = rsqrtf(q[j] * (1.0f / C) + 1e-5f);
            mn[j] = v[j] * rstd * ga + be;
        }

        unsigned long long acc2[LNR];
        #pragma unroll
        for (int j = 0; j < LNR; j++) acc2[j] = 0ull;
        #pragma unroll
        for (int c = 0; c < 32; c++) {
            #pragma unroll
            for (int j = 0; j < LNR; j++) {
                float mv = __shfl_sync(0xffffffffu, mn[j], c);
                ffma2(acc2[j], pack2(mv, mv), wp[c]);
            }
        }
        #pragma unroll
        for (int j = 0; j < LNR; j++) {
            float aA, aB;
            unpack2(acc2[j], aA, aB);
            g_ah[(size_t)(r0 + j) * C + lane] = __float2half(aA);
            g_bh[(size_t)(r0 + j) * C + lane] = __float2half(aB);
        }
    }
}

// -------------------------------------------------------------------------
// Kernel 2 (GEMM1, persistent): O[ic, jd] = (1/S) sum_s a[s,ic] b[s,jd]
// 288 CTAs (one wave @ 2/SM) x 32 tiles, fixed bi row. A panel resident.
// CTA tile 128x128, 4 warps (2x2), warp tile 64x64, trans-ldsm fragments.
// -------------------------------------------------------------------------
__global__ void __launch_bounds__(128, 2)
gemm1_mma() {
    extern __shared__ __align__(16) char smem[];

    const int bi  = blockIdx.x / 3;                // 0..95
    const int bj0 = (blockIdx.x % 3) * TPC;        // 0, 32, 64
    const int tid = threadIdx.x, lane = tid & 31, wid = tid >> 5;
    const int wm = wid & 1, wn = wid >> 1;
    const uint32_t sbase = smem_u32(smem);
    const uint32_t sB0 = sbase + G1_AB;

    float acc[4][8][4];
    #pragma unroll
    for (int tm = 0; tm < 4; tm++)
        #pragma unroll
        for (int tn = 0; tn < 8; tn++)
            #pragma unroll
            for (int q = 0; q < 4; q++) acc[tm][tn][q] = 0.f;

    // ---- load full A panel [256][128] once ----
    {
        const __half* A = g_ah + bi * 128;
        #pragma unroll
        for (int it = 0; it < 32; it++) {
            int idx = tid + it * 128, r = idx >> 4, ch = idx & 15;
            cp16(sbase + r * PITCHT + ch * 16, A + (size_t)r * IC + ch * 8);
        }
    }

    // B chunk loader: tile rep, kb (0..3, 64 k-rows each) -> buffer buf
    #define G1_LOADB(rep, kb, buf) do {                                        \
        const __half* B = g_bh + (size_t)((kb) * 64) * IC + (bj0 + (rep)) * 128;\
        uint32_t sB = sB0 + (buf) * G1_BT;                                     \
        _Pragma("unroll")                                                      \
        for (int it = 0; it < 8; it++) {                                       \
            int idx = tid + it * 128, r = idx >> 4, ch = idx & 15;             \
            cp16(sB + r * PITCHT + ch * 16, B + (size_t)r * IC + ch * 8);      \
        }                                                                      \
        asm volatile("cp.async.commit_group;" ::: "memory");                   \
    } while (0)

    G1_LOADB(0, 0, 0);   // group also flushes the A panel loads
    const float invS = 1.0f / MSA_S;
    const int r0 = lane >> 2, cp2 = (lane & 3) * 2;

    for (int it = 0; it < TPC * 4; it++) {
        int rep = it >> 2, kb = it & 3, buf = it & 1;
        if (it + 1 < TPC * 4) {
            G1_LOADB((it + 1) >> 2, (it + 1) & 3, buf ^ 1);
            asm volatile("cp.async.wait_group 1;" ::: "memory");
        } else {
            asm volatile("cp.async.wait_group 0;" ::: "memory");
        }
        __syncthreads();
        uint32_t sB = sB0 + buf * G1_BT;
        #pragma unroll
        for (int ks = 0; ks < 4; ks++) {
            uint32_t a[4][4];
            #pragma unroll
            for (int tm = 0; tm < 4; tm++) {
                int m0 = wm * 64 + tm * 16;
                ldsm4t(a[tm], sbase + (kb * 64 + ks * 16 + ((lane >> 4) << 3) + (lane & 7)) * PITCHT
                              + (m0 + ((lane >> 3) & 1) * 8) * 2);
            }
            uint32_t b[8][2];
            #pragma unroll
            for (int tq = 0; tq < 4; tq++) {
                int n0 = wn * 64 + tq * 16;
                uint32_t r[4];
                ldsm4t(r, sB + (ks * 16 + ((lane >> 3) & 1) * 8 + (lane & 7)) * PITCHT
                          + (n0 + ((lane >> 4) << 3)) * 2);
                b[2 * tq][0] = r[0]; b[2 * tq][1] = r[1];
                b[2 * tq + 1][0] = r[2]; b[2 * tq + 1][1] = r[3];
            }
            #pragma unroll
            for (int tm = 0; tm < 4; tm++)
                #pragma unroll
                for (int tn = 0; tn < 8; tn++)
                    mma16816(acc[tm][tn], a[tm], b[tn]);
        }
        __syncthreads();

        if (kb == 3) {      // epilogue for tile rep (overlaps next tile's B load)
            int bj = bj0 + rep;
            #pragma unroll
            for (int tm = 0; tm < 4; tm++) {
                #pragma unroll
                for (int tn = 0; tn < 8; tn++) {
                    int jd = bj * 128 + wn * 64 + tn * 8 + cp2;
                    int pcol = jd >> 5, d = jd & 31;
                    #pragma unroll
                    for (int h = 0; h < 2; h++) {
                        int ic = bi * 128 + wm * 64 + tm * 16 + r0 + h * 8;
                        __half2 hv;
                        hv.x = __float2half(acc[tm][tn][2 * h]     * invS);
                        hv.y = __float2half(acc[tm][tn][2 * h + 1] * invS);
                        size_t off = ((size_t)(ic >> 5) * NRES + pcol) * CD
                                     + (ic & 31) * 32 + d;
                        *(__half2*)(g_o + off) = hv;
                        acc[tm][tn][2 * h] = 0.f;
                        acc[tm][tn][2 * h + 1] = 0.f;
                    }
                }
            }
        }
    }
    #undef G1_LOADB
}

// -------------------------------------------------------------------------
// Kernel 3 (GEMM2, persistent): z[m,e] = O[m,:] @ W3[:,e] + b3
// 288 CTAs x 4 m-tiles. K = 1024, 64k-chunks, 3-stage pipeline running
// continuously across tile boundaries. 4 warps, warp tile 64x64.
// -------------------------------------------------------------------------
__global__ void __launch_bounds__(128, 2)
gemm2_mma(const float* __restrict__ b3, float* __restrict__ z) {
    extern __shared__ __align__(16) char smem[];

    const int mb0 = blockIdx.x * TP2;
    const int tid = threadIdx.x, lane = tid & 31, wid = tid >> 5;
    const int wm = wid & 1, wn = wid >> 1;
    const uint32_t sbase = smem_u32(smem);

    float acc[4][8][4];
    #pragma unroll
    for (int tm = 0; tm < 4; tm++)
        #pragma unroll
        for (int tn = 0; tn < 8; tn++)
            #pragma unroll
            for (int q = 0; q < 4; q++) acc[tm][tn][q] = 0.f;

    #define G2_LOAD(mb, kb, buf) do {                                          \
        int k0 = (kb) * 64;                                                    \
        const __half* A = g_o + (size_t)((mb) * 128) * CD + k0;                \
        const __half* B = g_w3h + (size_t)k0 * CZ;                             \
        uint32_t sA = sbase + (buf) * G2_STG, sB = sA + TBA2;                  \
        _Pragma("unroll")                                                      \
        for (int it = 0; it < 8; it++) {                                       \
            int idx = tid + it * 128;                                          \
            int ra = idx >> 3, ca = idx & 7;                                   \
            cp16(sA + ra * PITCHA2 + ca * 16, A + (size_t)ra * CD + ca * 8);   \
            int rb = idx >> 4, cb = idx & 15;                                  \
            cp16(sB + rb * PITCHT + cb * 16, B + (size_t)rb * CZ + cb * 8);    \
        }                                                                      \
        asm volatile("cp.async.commit_group;" ::: "memory");                   \
    } while (0)

    const int NIT = TP2 * 16;
    G2_LOAD(mb0, 0, 0);
    G2_LOAD(mb0, 1, 1);
    const int r0 = lane >> 2, cp2 = (lane & 3) * 2;

    for (int it = 0; it < NIT; it++) {
        int tile = it >> 4, kb = it & 15, buf = it % 3;
        if (it + 2 < NIT) {
            G2_LOAD(mb0 + ((it + 2) >> 4), (it + 2) & 15, (it + 2) % 3);
            asm volatile("cp.async.wait_group 2;" ::: "memory");
        } else if (it + 1 < NIT) {
            asm volatile("cp.async.wait_group 1;" ::: "memory");
        } else {
            asm volatile("cp.async.wait_group 0;" ::: "memory");
        }
        __syncthreads();
        uint32_t sA = sbase + buf * G2_STG, sB = sA + TBA2;
        #pragma unroll
        for (int ks = 0; ks < 4; ks++) {
            uint32_t a[4][4];
            #pragma unroll
            for (int tm = 0; tm < 4; tm++)
                ldsm4(a[tm], sA + (wm * 64 + tm * 16 + (lane & 15)) * PITCHA2
                             + ks * 32 + (lane >> 4) * 16);
            uint32_t b[8][2];
            #pragma unroll
            for (int tq = 0; tq < 4; tq++) {
                int n0 = wn * 64 + tq * 16;
                uint32_t r[4];
                ldsm4t(r, sB + (ks * 16 + ((lane >> 3) & 1) * 8 + (lane & 7)) * PITCHT
                          + (n0 + ((lane >> 4) << 3)) * 2);
                b[2 * tq][0] = r[0]; b[2 * tq][1] = r[1];
                b[2 * tq + 1][0] = r[2]; b[2 * tq + 1][1] = r[3];
            }
            #pragma unroll
            for (int tm = 0; tm < 4; tm++)
                #pragma unroll
                for (int tn = 0; tn < 8; tn++)
                    mma16816(acc[tm][tn], a[tm], b[tn]);
        }
        __syncthreads();

        if (kb == 15) {     // epilogue for this m-tile; pipeline keeps running
            int mb = mb0 + tile;
            #pragma unroll
            for (int tm = 0; tm < 4; tm++) {
                #pragma unroll
                for (int tn = 0; tn < 8; tn++) {
                    int e = wn * 64 + tn * 8 + cp2;
                    float be0 = __ldg(b3 + e), be1 = __ldg(b3 + e + 1);
                    #pragma unroll
                    for (int h = 0; h < 2; h++) {
                        size_t mrow = (size_t)mb * 128 + wm * 64 + tm * 16 + r0 + h * 8;
                        float2 v;
                        v.x = acc[tm][tn][2 * h]     + be0;
                        v.y = acc[tm][tn][2 * h + 1] + be1;
                        *(float2*)(z + mrow * CZ + e) = v;
                        acc[tm][tn][2 * h] = 0.f;
                        acc[tm][tn][2 * h + 1] = 0.f;
                    }
                }
            }
        }
    }
    #undef G2_LOAD
}

// -------------------------------------------------------------------------
extern "C" void kernel_launch(void* const* d_in, const int* in_sizes, int n_in,
                              void* d_out, int out_size) {
    const float* m     = (const float*)d_in[0];
    const float* gamma = (const float*)d_in[1];
    const float* beta  = (const float*)d_in[2];
    const float* W1    = (const float*)d_in[3];
    const float* W2    = (const float*)d_in[4];
    const float* W3    = (const float*)d_in[5];
    const float* b3    = (const float*)d_in[6];
    float* z = (float*)d_out;
    (void)in_sizes; (void)n_in; (void)out_size;

    cudaFuncSetAttribute(gemm1_mma,
                         cudaFuncAttributeMaxDynamicSharedMemorySize, G1_SMEM);
    cudaFuncSetAttribute(gemm2_mma,
                         cudaFuncAttributeMaxDynamicSharedMemorySize, G2_SMEM);

    ln_proj_kernel<<<2048, 128>>>(m, gamma, beta, W1, W2, W3);
    gemm1_mma<<<96 * (96 / TPC), 128, G1_SMEM>>>();        // 288 CTAs
    gemm2_mma<<<(NPAIR / 128) / TP2, 128, G2_SMEM>>>(b3, z); // 288 CTAs
}

// round 16
// speedup vs baseline: 1.0046x; 1.0046x over previous
#include <cuda_runtime.h>
#include <cuda_fp16.h>
#include <cstdint>

#define MSA_S 256
#define NRES  384
#define C     32
#define CZ    128
#define IC    (NRES * C)          // 12288
#define NPAIR (NRES * NRES)       // 147456
#define CD    (C * C)             // 1024

// ------------------------------ scratch ----------------------------------
__device__ __half g_ah[MSA_S * IC];                // LN(m)@W1  [s][ic] fp16
__device__ __half g_bh[MSA_S * IC];                // LN(m)@W2  [s][ic] fp16
__device__ __half g_w3h[CD * CZ];                  // [cd][e] fp16
__device__ __half g_o[(size_t)NPAIR * CD];         // 302 MB fp16

// --------------------------- helpers -------------------------------------
__device__ __forceinline__ uint32_t smem_u32(const void* p) {
    uint32_t a;
    asm("{ .reg .u64 t; cvta.to.shared.u64 t, %1; cvt.u32.u64 %0, t; }"
        : "=r"(a) : "l"(p));
    return a;
}
__device__ __forceinline__ void cp16(uint32_t saddr, const void* g) {
    asm volatile("cp.async.cg.shared.global [%0], [%1], 16;"
                 :: "r"(saddr), "l"(g) : "memory");
}
__device__ __forceinline__ void ldsm4(uint32_t* r, uint32_t addr) {
    asm volatile("ldmatrix.sync.aligned.m8n8.x4.shared.b16 {%0,%1,%2,%3}, [%4];"
                 : "=r"(r[0]), "=r"(r[1]), "=r"(r[2]), "=r"(r[3]) : "r"(addr));
}
__device__ __forceinline__ void ldsm4t(uint32_t* r, uint32_t addr) {
    asm volatile("ldmatrix.sync.aligned.m8n8.x4.trans.shared.b16 {%0,%1,%2,%3}, [%4];"
                 : "=r"(r[0]), "=r"(r[1]), "=r"(r[2]), "=r"(r[3]) : "r"(addr));
}
__device__ __forceinline__ void mma16816(float* d, const uint32_t* a,
                                         const uint32_t* b) {
    asm volatile(
        "mma.sync.aligned.m16n8k16.row.col.f32.f16.f16.f32 "
        "{%0,%1,%2,%3}, {%4,%5,%6,%7}, {%8,%9}, {%0,%1,%2,%3};"
        : "+f"(d[0]), "+f"(d[1]), "+f"(d[2]), "+f"(d[3])
        : "r"(a[0]), "r"(a[1]), "r"(a[2]), "r"(a[3]), "r"(b[0]), "r"(b[1]));
}

#define PITCHT  272               // [k][128] tile pitch: 256B data + 16B pad
// gemm1: A panel resident [256k][128m]; B chunks 64k x 128 double-buffered
#define G1_AB    (256 * PITCHT)             // 69632
#define G1_BT    (64 * PITCHT)              // 17408
#define G1_SMEM  (G1_AB + 2 * G1_BT)        // 104448
#define TPC      32                         // gemm1 tiles per CTA (same bi row)
// gemm2: A [128m][64k] pitch 144; B [64k][128e] pitch 272; 3-stage
#define PITCHA2  144
#define TBA2     (128 * PITCHA2)            // 18432
#define TBB2     G1_BT                      // 17408
#define G2_STG   (TBA2 + TBB2)              // 35840
#define G2_SMEM  (3 * G2_STG)               // 107520

// -------------------------------------------------------------------------
// Kernel 1: fused LayerNorm + dual projection -> fp16 [s][ic].
// 4 rows per warp iteration; 128-thread CTAs (occupancy). Single fused
// reduction pass: sum(x) and sum(x^2) reduced together, var = E[x^2]-mu^2.
// Blocks < 128 also convert their slice of W3 to fp16.
// -------------------------------------------------------------------------
#define LNR 4
__global__ void __launch_bounds__(128)
ln_proj_kernel(const float* __restrict__ m,
               const float* __restrict__ gamma,
               const float* __restrict__ beta,
               const float* __restrict__ W1,
               const float* __restrict__ W2,
               const float* __restrict__ W3) {
    const int lane = threadIdx.x & 31, wid = threadIdx.x >> 5;

    if (blockIdx.x < 128) {          // W3 convert: 128 blocks x 1024 floats
        int i = blockIdx.x * 1024 + threadIdx.x * 8;
        float4 v0 = *(const float4*)(W3 + i);
        float4 v1 = *(const float4*)(W3 + i + 4);
        *(__half2*)(g_w3h + i)     = __floats2half2_rn(v0.x, v0.y);
        *(__half2*)(g_w3h + i + 2) = __floats2half2_rn(v0.z, v0.w);
        *(__half2*)(g_w3h + i + 4) = __floats2half2_rn(v1.x, v1.y);
        *(__half2*)(g_w3h + i + 6) = __floats2half2_rn(v1.z, v1.w);
    }

    float w1c[32], w2c[32];
    #pragma unroll
    for (int c = 0; c < 32; c++) {
        w1c[c] = W1[c * C + lane];
        w2c[c] = W2[c * C + lane];
    }
    const float ga = gamma[lane], be = beta[lane];
    const int stride = gridDim.x * 4 * LNR;         // rows per sweep

    for (int r0 = (blockIdx.x * 4 + wid) * LNR; r0 < MSA_S * NRES; r0 += stride) {
        float v[LNR], s[LNR], q[LNR], mn[LNR];
        #pragma unroll
        for (int j = 0; j < LNR; j++)
            v[j] = m[(size_t)(r0 + j) * C + lane];
        // fused single-pass reduction: sum and sum-of-squares together
        #pragma unroll
        for (int j = 0; j < LNR; j++) {
            s[j] = v[j];
            q[j] = v[j] * v[j];
        }
        #pragma unroll
        for (int o = 16; o; o >>= 1) {
            #pragma unroll
            for (int j = 0; j < LNR; j++) {
                s[j] += __shfl_xor_sync(0xffffffffu, s[j], o);
                q[j] += __shfl_xor_sync(0xffffffffu, q[j], o);
            }
        }
        #pragma unroll
        for (int j = 0; j < LNR; j++) {
            float mu  = s[j] * (1.0f / C);
            float var = q[j] * (1.0f / C) - mu * mu;   // E[x^2] - mu^2
            float rstd = rsqrtf(var + 1e-5f);
            mn[j] = (v[j] - mu) * rstd * ga + be;
        }

        float aA[LNR], aB[LNR];
        #pragma unroll
        for (int j = 0; j < LNR; j++) { aA[j] = 0.f; aB[j] = 0.f; }
        #pragma unroll
        for (int c = 0; c < 32; c++) {
            #pragma unroll
            for (int j = 0; j < LNR; j++) {
                float mv = __shfl_sync(0xffffffffu, mn[j], c);
                aA[j] += mv * w1c[c];
                aB[j] += mv * w2c[c];
            }
        }
        #pragma unroll
        for (int j = 0; j < LNR; j++) {
            g_ah[(size_t)(r0 + j) * C + lane] = __float2half(aA[j]);
            g_bh[(size_t)(r0 + j) * C + lane] = __float2half(aB[j]);
        }
    }
}

// -------------------------------------------------------------------------
// Kernel 2 (GEMM1, persistent): O[ic, jd] = (1/S) sum_s a[s,ic] b[s,jd]
// 288 CTAs (one wave @ 2/SM) x 32 tiles, fixed bi row. A panel resident.
// CTA tile 128x128, 4 warps (2x2), warp tile 64x64, trans-ldsm fragments.
// -------------------------------------------------------------------------
__global__ void __launch_bounds__(128, 2)
gemm1_mma() {
    extern __shared__ __align__(16) char smem[];

    const int bi  = blockIdx.x / 3;                // 0..95
    const int bj0 = (blockIdx.x % 3) * TPC;        // 0, 32, 64
    const int tid = threadIdx.x, lane = tid & 31, wid = tid >> 5;
    const int wm = wid & 1, wn = wid >> 1;
    const uint32_t sbase = smem_u32(smem);
    const uint32_t sB0 = sbase + G1_AB;

    float acc[4][8][4];
    #pragma unroll
    for (int tm = 0; tm < 4; tm++)
        #pragma unroll
        for (int tn = 0; tn < 8; tn++)
            #pragma unroll
            for (int q = 0; q < 4; q++) acc[tm][tn][q] = 0.f;

    // ---- load full A panel [256][128] once ----
    {
        const __half* A = g_ah + bi * 128;
        #pragma unroll
        for (int it = 0; it < 32; it++) {
            int idx = tid + it * 128, r = idx >> 4, ch = idx & 15;
            cp16(sbase + r * PITCHT + ch * 16, A + (size_t)r * IC + ch * 8);
        }
    }

    // B chunk loader: tile rep, kb (0..3, 64 k-rows each) -> buffer buf
    #define G1_LOADB(rep, kb, buf) do {                                        \
        const __half* B = g_bh + (size_t)((kb) * 64) * IC + (bj0 + (rep)) * 128;\
        uint32_t sB = sB0 + (buf) * G1_BT;                                     \
        _Pragma("unroll")                                                      \
        for (int it = 0; it < 8; it++) {                                       \
            int idx = tid + it * 128, r = idx >> 4, ch = idx & 15;             \
            cp16(sB + r * PITCHT + ch * 16, B + (size_t)r * IC + ch * 8);      \
        }                                                                      \
        asm volatile("cp.async.commit_group;" ::: "memory");                   \
    } while (0)

    G1_LOADB(0, 0, 0);   // group also flushes the A panel loads
    const float invS = 1.0f / MSA_S;
    const int r0 = lane >> 2, cp2 = (lane & 3) * 2;

    for (int it = 0; it < TPC * 4; it++) {
        int rep = it >> 2, kb = it & 3, buf = it & 1;
        if (it + 1 < TPC * 4) {
            G1_LOADB((it + 1) >> 2, (it + 1) & 3, buf ^ 1);
            asm volatile("cp.async.wait_group 1;" ::: "memory");
        } else {
            asm volatile("cp.async.wait_group 0;" ::: "memory");
        }
        __syncthreads();
        uint32_t sB = sB0 + buf * G1_BT;
        #pragma unroll
        for (int ks = 0; ks < 4; ks++) {
            uint32_t a[4][4];
            #pragma unroll
            for (int tm = 0; tm < 4; tm++) {
                int m0 = wm * 64 + tm * 16;
                ldsm4t(a[tm], sbase + (kb * 64 + ks * 16 + ((lane >> 4) << 3) + (lane & 7)) * PITCHT
                              + (m0 + ((lane >> 3) & 1) * 8) * 2);
            }
            uint32_t b[8][2];
            #pragma unroll
            for (int tq = 0; tq < 4; tq++) {
                int n0 = wn * 64 + tq * 16;
                uint32_t r[4];
                ldsm4t(r, sB + (ks * 16 + ((lane >> 3) & 1) * 8 + (lane & 7)) * PITCHT
                          + (n0 + ((lane >> 4) << 3)) * 2);
                b[2 * tq][0] = r[0]; b[2 * tq][1] = r[1];
                b[2 * tq + 1][0] = r[2]; b[2 * tq + 1][1] = r[3];
            }
            #pragma unroll
            for (int tm = 0; tm < 4; tm++)
                #pragma unroll
                for (int tn = 0; tn < 8; tn++)
                    mma16816(acc[tm][tn], a[tm], b[tn]);
        }
        __syncthreads();

        if (kb == 3) {      // epilogue for tile rep (overlaps next tile's B load)
            int bj = bj0 + rep;
            #pragma unroll
            for (int tm = 0; tm < 4; tm++) {
                #pragma unroll
                for (int tn = 0; tn < 8; tn++) {
                    int jd = bj * 128 + wn * 64 + tn * 8 + cp2;
                    int pcol = jd >> 5, d = jd & 31;
                    #pragma unroll
                    for (int h = 0; h < 2; h++) {
                        int ic = bi * 128 + wm * 64 + tm * 16 + r0 + h * 8;
                        __half2 hv;
                        hv.x = __float2half(acc[tm][tn][2 * h]     * invS);
                        hv.y = __float2half(acc[tm][tn][2 * h + 1] * invS);
                        size_t off = ((size_t)(ic >> 5) * NRES + pcol) * CD
                                     + (ic & 31) * 32 + d;
                        *(__half2*)(g_o + off) = hv;
                        acc[tm][tn][2 * h] = 0.f;
                        acc[tm][tn][2 * h + 1] = 0.f;
                    }
                }
            }
        }
    }
    #undef G1_LOADB
}

// -------------------------------------------------------------------------
// Kernel 3 (GEMM2): z[m,e] = O[m,:] @ W3[:,e] + b3
// M = 147456, N = 128, K = 1024, 64k-chunks, 3-stage pipeline.
// 4 warps, warp tile 64x64. (1152-CTA non-persistent — best measured.)
// -------------------------------------------------------------------------
__global__ void __launch_bounds__(128, 2)
gemm2_mma(const float* __restrict__ b3, float* __restrict__ z) {
    extern __shared__ __align__(16) char smem[];

    const int mb = blockIdx.x;
    const int tid = threadIdx.x, lane = tid & 31, wid = tid >> 5;
    const int wm = wid & 1, wn = wid >> 1;
    const uint32_t sbase = smem_u32(smem);

    float acc[4][8][4];
    #pragma unroll
    for (int tm = 0; tm < 4; tm++)
        #pragma unroll
        for (int tn = 0; tn < 8; tn++)
            #pragma unroll
            for (int q = 0; q < 4; q++) acc[tm][tn][q] = 0.f;

    #define G2_LOAD(kb, buf) do {                                              \
        int k0 = (kb) * 64;                                                    \
        const __half* A = g_o + (size_t)(mb * 128) * CD + k0;                  \
        const __half* B = g_w3h + (size_t)k0 * CZ;                             \
        uint32_t sA = sbase + (buf) * G2_STG, sB = sA + TBA2;                  \
        _Pragma("unroll")                                                      \
        for (int it = 0; it < 8; it++) {                                       \
            int idx = tid + it * 128;                                          \
            int ra = idx >> 3, ca = idx & 7;                                   \
            cp16(sA + ra * PITCHA2 + ca * 16, A + (size_t)ra * CD + ca * 8);   \
            int rb = idx >> 4, cb = idx & 15;                                  \
            cp16(sB + rb * PITCHT + cb * 16, B + (size_t)rb * CZ + cb * 8);    \
        }                                                                      \
        asm volatile("cp.async.commit_group;" ::: "memory");                   \
    } while (0)

    G2_LOAD(0, 0);
    G2_LOAD(1, 1);
    for (int kb = 0; kb < 16; kb++) {
        int buf = kb % 3;
        if (kb + 2 < 16) {
            G2_LOAD(kb + 2, (kb + 2) % 3);
            asm volatile("cp.async.wait_group 2;" ::: "memory");
        } else if (kb + 1 < 16) {
            asm volatile("cp.async.wait_group 1;" ::: "memory");
        } else {
            asm volatile("cp.async.wait_group 0;" ::: "memory");
        }
        __syncthreads();
        uint32_t sA = sbase + buf * G2_STG, sB = sA + TBA2;
        #pragma unroll
        for (int ks = 0; ks < 4; ks++) {
            uint32_t a[4][4];
            #pragma unroll
            for (int tm = 0; tm < 4; tm++)
                ldsm4(a[tm], sA + (wm * 64 + tm * 16 + (lane & 15)) * PITCHA2
                             + ks * 32 + (lane >> 4) * 16);
            uint32_t b[8][2];
            #pragma unroll
            for (int tq = 0; tq < 4; tq++) {
                int n0 = wn * 64 + tq * 16;
                uint32_t r[4];
                ldsm4t(r, sB + (ks * 16 + ((lane >> 3) & 1) * 8 + (lane & 7)) * PITCHT
                          + (n0 + ((lane >> 4) << 3)) * 2);
                b[2 * tq][0] = r[0]; b[2 * tq][1] = r[1];
                b[2 * tq + 1][0] = r[2]; b[2 * tq + 1][1] = r[3];
            }
            #pragma unroll
            for (int tm = 0; tm < 4; tm++)
                #pragma unroll
                for (int tn = 0; tn < 8; tn++)
                    mma16816(acc[tm][tn], a[tm], b[tn]);
        }
        __syncthreads();
    }

    const int r0 = lane >> 2, cp2 = (lane & 3) * 2;
    #pragma unroll
    for (int tm = 0; tm < 4; tm++) {
        #pragma unroll
        for (int tn = 0; tn < 8; tn++) {
            int e = wn * 64 + tn * 8 + cp2;
            float be0 = __ldg(b3 + e), be1 = __ldg(b3 + e + 1);
            #pragma unroll
            for (int h = 0; h < 2; h++) {
                size_t mrow = (size_t)mb * 128 + wm * 64 + tm * 16 + r0 + h * 8;
                float2 v;
                v.x = acc[tm][tn][2 * h]     + be0;
                v.y = acc[tm][tn][2 * h + 1] + be1;
                *(float2*)(z + mrow * CZ + e) = v;
            }
        }
    }
    #undef G2_LOAD
}

// -------------------------------------------------------------------------
extern "C" void kernel_launch(void* const* d_in, const int* in_sizes, int n_in,
                              void* d_out, int out_size) {
    const float* m     = (const float*)d_in[0];
    const float* gamma = (const float*)d_in[1];
    const float* beta  = (const float*)d_in[2];
    const float* W1    = (const float*)d_in[3];
    const float* W2    = (const float*)d_in[4];
    const float* W3    = (const float*)d_in[5];
    const float* b3    = (const float*)d_in[6];
    float* z = (float*)d_out;
    (void)in_sizes; (void)n_in; (void)out_size;

    cudaFuncSetAttribute(gemm1_mma,
                         cudaFuncAttributeMaxDynamicSharedMemorySize, G1_SMEM);
    cudaFuncSetAttribute(gemm2_mma,
                         cudaFuncAttributeMaxDynamicSharedMemorySize, G2_SMEM);

    ln_proj_kernel<<<2048, 128>>>(m, gamma, beta, W1, W2, W3);
    gemm1_mma<<<96 * (96 / TPC), 128, G1_SMEM>>>();   // 288 CTAs, one wave
    gemm2_mma<<<NPAIR / 128, 128, G2_SMEM>>>(b3, z);  // 1152 CTAs
}

// round 17
// speedup vs baseline: 1.0316x; 1.0269x over previous
#include <cuda_runtime.h>
#include <cuda_fp16.h>
#include <cstdint>

#define MSA_S 256
#define NRES  384
#define C     32
#define CZ    128
#define IC    (NRES * C)          // 12288
#define NPAIR (NRES * NRES)       // 147456
#define CD    (C * C)             // 1024
#define NROWS (MSA_S * NRES)      // 98304

// ------------------------------ scratch ----------------------------------
__device__ __half g_ah[MSA_S * IC];                // LN(m)@W1  [s][ic] fp16
__device__ __half g_bh[MSA_S * IC];                // LN(m)@W2  [s][ic] fp16
__device__ __half g_w3h[CD * CZ];                  // [cd][e] fp16
__device__ __half g_o[(size_t)NPAIR * CD];         // 302 MB fp16

// --------------------------- helpers -------------------------------------
__device__ __forceinline__ uint32_t smem_u32(const void* p) {
    uint32_t a;
    asm("{ .reg .u64 t; cvta.to.shared.u64 t, %1; cvt.u32.u64 %0, t; }"
        : "=r"(a) : "l"(p));
    return a;
}
__device__ __forceinline__ void cp16(uint32_t saddr, const void* g) {
    asm volatile("cp.async.cg.shared.global [%0], [%1], 16;"
                 :: "r"(saddr), "l"(g) : "memory");
}
__device__ __forceinline__ void ldsm4(uint32_t* r, uint32_t addr) {
    asm volatile("ldmatrix.sync.aligned.m8n8.x4.shared.b16 {%0,%1,%2,%3}, [%4];"
                 : "=r"(r[0]), "=r"(r[1]), "=r"(r[2]), "=r"(r[3]) : "r"(addr));
}
__device__ __forceinline__ void ldsm4t(uint32_t* r, uint32_t addr) {
    asm volatile("ldmatrix.sync.aligned.m8n8.x4.trans.shared.b16 {%0,%1,%2,%3}, [%4];"
                 : "=r"(r[0]), "=r"(r[1]), "=r"(r[2]), "=r"(r[3]) : "r"(addr));
}
__device__ __forceinline__ void mma16816(float* d, const uint32_t* a,
                                         const uint32_t* b) {
    asm volatile(
        "mma.sync.aligned.m16n8k16.row.col.f32.f16.f16.f32 "
        "{%0,%1,%2,%3}, {%4,%5,%6,%7}, {%8,%9}, {%0,%1,%2,%3};"
        : "+f"(d[0]), "+f"(d[1]), "+f"(d[2]), "+f"(d[3])
        : "r"(a[0]), "r"(a[1]), "r"(a[2]), "r"(a[3]), "r"(b[0]), "r"(b[1]));
}

#define PITCHT  272               // [k][128] tile pitch: 256B data + 16B pad
// gemm1: A panel resident [256k][128m]; B chunks 64k x 128 double-buffered
#define G1_AB    (256 * PITCHT)             // 69632
#define G1_BT    (64 * PITCHT)              // 17408
#define G1_SMEM  (G1_AB + 2 * G1_BT)        // 104448
#define TPC      32                         // gemm1 tiles per CTA (same bi row)
// gemm2: A [128m][64k] pitch 144; B [64k][128e] pitch 272; 3-stage
#define PITCHA2  144
#define TBA2     (128 * PITCHA2)            // 18432
#define TBB2     G1_BT                      // 17408
#define G2_STG   (TBA2 + TBB2)              // 35840
#define G2_SMEM  (3 * G2_STG)               // 107520

// -------------------------------------------------------------------------
// Kernel 1: fused LayerNorm + dual projection via tensor cores.
// a = rstd*(m@Wg - mu*gs) + cb   with Wg = diag(gamma)*[W1|W2],
//   gs = gamma@[W1|W2], cb = beta@[W1|W2].
// Per warp: 16 rows. Stats: float4/lane, 8 lanes/row, 3 shfl levels.
// Projection: mma.m16n8k16, W fragments register-resident.
// Blocks < 128 also convert their slice of W3 to fp16.
// -------------------------------------------------------------------------
#define LA_PITCH 80                         // A tile [16 rows][32 c] fp16
__global__ void __launch_bounds__(128)
ln_proj_kernel(const float* __restrict__ m,
               const float* __restrict__ gamma,
               const float* __restrict__ beta,
               const float* __restrict__ W1,
               const float* __restrict__ W2,
               const float* __restrict__ W3) {
    __shared__ __align__(16) char sA[4 * 16 * LA_PITCH];    // 5120 B
    __shared__ float2 sStats[4][16];
    __shared__ float  sGs[64], sCb[64];
    __shared__ __align__(16) char sW[32 * PITCHA2];         // [c][64e] fp16

    const int tid = threadIdx.x, lane = tid & 31, wid = tid >> 5;

    if (blockIdx.x < 128) {          // W3 convert: 128 blocks x 1024 floats
        int i = blockIdx.x * 1024 + tid * 8;
        float4 v0 = *(const float4*)(W3 + i);
        float4 v1 = *(const float4*)(W3 + i + 4);
        *(__half2*)(g_w3h + i)     = __floats2half2_rn(v0.x, v0.y);
        *(__half2*)(g_w3h + i + 2) = __floats2half2_rn(v0.z, v0.w);
        *(__half2*)(g_w3h + i + 4) = __floats2half2_rn(v1.x, v1.y);
        *(__half2*)(g_w3h + i + 6) = __floats2half2_rn(v1.z, v1.w);
    }

    // ---- per-CTA prep: Wg fp16 tile + gs/cb vectors ----
    #pragma unroll
    for (int i = 0; i < 16; i++) {               // 2048 = 128 thr * 16
        int idx = tid + i * 128;
        int c = idx >> 6, e = idx & 63;
        float w = (e < 32) ? W1[c * C + e] : W2[c * C + (e - 32)];
        *(__half*)(sW + c * PITCHA2 + e * 2) = __float2half(w * gamma[c]);
    }
    if (tid < 64) {
        float gs = 0.f, cb = 0.f;
        #pragma unroll
        for (int c = 0; c < 32; c++) {
            float w = (tid < 32) ? W1[c * C + tid] : W2[c * C + (tid - 32)];
            gs += gamma[c] * w;
            cb += beta[c]  * w;
        }
        sGs[tid] = gs; sCb[tid] = cb;
    }
    __syncthreads();

    // ---- load W fragments once (B for mma, col-major via trans ldsm) ----
    const uint32_t sWu = smem_u32(sW);
    uint32_t bf[2][8][2];
    #pragma unroll
    for (int ks = 0; ks < 2; ks++) {
        #pragma unroll
        for (int tq = 0; tq < 4; tq++) {
            int n0 = tq * 16;
            uint32_t r[4];
            ldsm4t(r, sWu + (ks * 16 + ((lane >> 3) & 1) * 8 + (lane & 7)) * PITCHA2
                      + (n0 + ((lane >> 4) << 3)) * 2);
            bf[ks][2 * tq][0] = r[0]; bf[ks][2 * tq][1] = r[1];
            bf[ks][2 * tq + 1][0] = r[2]; bf[ks][2 * tq + 1][1] = r[3];
        }
    }

    const uint32_t sAw = smem_u32(sA) + wid * 16 * LA_PITCH;

    for (int base = blockIdx.x * 64; base < NROWS; base += gridDim.x * 64) {
        const int wrow = base + wid * 16;        // this warp's 16 rows

        // ---- load m rows, stats, fp16 tile ----
        #pragma unroll
        for (int i = 0; i < 4; i++) {
            int idx = i * 32 + lane;
            int row = idx >> 3, col4 = idx & 7;  // 8 lanes per row
            float4 v = *(const float4*)(m + (size_t)(wrow + row) * C + col4 * 4);
            float s = v.x + v.y + v.z + v.w;
            float q = v.x * v.x + v.y * v.y + v.z * v.z + v.w * v.w;
            #pragma unroll
            for (int o = 1; o < 8; o <<= 1) {
                s += __shfl_xor_sync(0xffffffffu, s, o);
                q += __shfl_xor_sync(0xffffffffu, q, o);
            }
            if ((lane & 7) == 0) {
                float mu  = s * (1.0f / C);
                float var = q * (1.0f / C) - mu * mu;
                sStats[wid][row] = make_float2(mu, rsqrtf(var + 1e-5f));
            }
            __half2 h0 = __floats2half2_rn(v.x, v.y);
            __half2 h1 = __floats2half2_rn(v.z, v.w);
            *(uint2*)(sA + wid * 16 * LA_PITCH + row * LA_PITCH + col4 * 8)
                = make_uint2(*(uint32_t*)&h0, *(uint32_t*)&h1);
        }
        __syncwarp();

        // ---- A fragments + MMA: t = m16 x 64, K = 32 ----
        uint32_t af[2][4];
        #pragma unroll
        for (int ks = 0; ks < 2; ks++)
            ldsm4(af[ks], sAw + (lane & 15) * LA_PITCH + ks * 32 + (lane >> 4) * 16);

        float acc[8][4];
        #pragma unroll
        for (int tn = 0; tn < 8; tn++)
            #pragma unroll
            for (int q = 0; q < 4; q++) acc[tn][q] = 0.f;
        #pragma unroll
        for (int ks = 0; ks < 2; ks++)
            #pragma unroll
            for (int tn = 0; tn < 8; tn++)
                mma16816(acc[tn], af[ks], bf[ks][tn]);

        // ---- epilogue: a = rstd*(t - mu*gs) + cb, store fp16 ----
        const int r0 = lane >> 2, cp2 = (lane & 3) * 2;
        float2 st0 = sStats[wid][r0];
        float2 st1 = sStats[wid][r0 + 8];
        #pragma unroll
        for (int tn = 0; tn < 8; tn++) {
            int e = tn * 8 + cp2;
            float gs0 = sGs[e], gs1 = sGs[e + 1];
            float cb0 = sCb[e], cb1 = sCb[e + 1];
            #pragma unroll
            for (int h = 0; h < 2; h++) {
                float2 st = h ? st1 : st0;
                int row = wrow + r0 + h * 8;
                float o0 = st.y * (acc[tn][2 * h]     - st.x * gs0) + cb0;
                float o1 = st.y * (acc[tn][2 * h + 1] - st.x * gs1) + cb1;
                __half2 hv = __floats2half2_rn(o0, o1);
                if (e < 32)
                    *(__half2*)(g_ah + (size_t)row * C + e) = hv;
                else
                    *(__half2*)(g_bh + (size_t)row * C + (e - 32)) = hv;
            }
        }
        __syncwarp();
    }
}

// -------------------------------------------------------------------------
// Kernel 2 (GEMM1, persistent): O[ic, jd] = (1/S) sum_s a[s,ic] b[s,jd]
// 288 CTAs (one wave @ 2/SM) x 32 tiles, fixed bi row. A panel resident.
// CTA tile 128x128, 4 warps (2x2), warp tile 64x64, trans-ldsm fragments.
// -------------------------------------------------------------------------
__global__ void __launch_bounds__(128, 2)
gemm1_mma() {
    extern __shared__ __align__(16) char smem[];

    const int bi  = blockIdx.x / 3;                // 0..95
    const int bj0 = (blockIdx.x % 3) * TPC;        // 0, 32, 64
    const int tid = threadIdx.x, lane = tid & 31, wid = tid >> 5;
    const int wm = wid & 1, wn = wid >> 1;
    const uint32_t sbase = smem_u32(smem);
    const uint32_t sB0 = sbase + G1_AB;

    float acc[4][8][4];
    #pragma unroll
    for (int tm = 0; tm < 4; tm++)
        #pragma unroll
        for (int tn = 0; tn < 8; tn++)
            #pragma unroll
            for (int q = 0; q < 4; q++) acc[tm][tn][q] = 0.f;

    // ---- load full A panel [256][128] once ----
    {
        const __half* A = g_ah + bi * 128;
        #pragma unroll
        for (int it = 0; it < 32; it++) {
            int idx = tid + it * 128, r = idx >> 4, ch = idx & 15;
            cp16(sbase + r * PITCHT + ch * 16, A + (size_t)r * IC + ch * 8);
        }
    }

    #define G1_LOADB(rep, kb, buf) do {                                        \
        const __half* B = g_bh + (size_t)((kb) * 64) * IC + (bj0 + (rep)) * 128;\
        uint32_t sB = sB0 + (buf) * G1_BT;                                     \
        _Pragma("unroll")                                                      \
        for (int it = 0; it < 8; it++) {                                       \
            int idx = tid + it * 128, r = idx >> 4, ch = idx & 15;             \
            cp16(sB + r * PITCHT + ch * 16, B + (size_t)r * IC + ch * 8);      \
        }                                                                      \
        asm volatile("cp.async.commit_group;" ::: "memory");                   \
    } while (0)

    G1_LOADB(0, 0, 0);
    const float invS = 1.0f / MSA_S;
    const int r0 = lane >> 2, cp2 = (lane & 3) * 2;

    for (int it = 0; it < TPC * 4; it++) {
        int rep = it >> 2, kb = it & 3, buf = it & 1;
        if (it + 1 < TPC * 4) {
            G1_LOADB((it + 1) >> 2, (it + 1) & 3, buf ^ 1);
            asm volatile("cp.async.wait_group 1;" ::: "memory");
        } else {
            asm volatile("cp.async.wait_group 0;" ::: "memory");
        }
        __syncthreads();
        uint32_t sB = sB0 + buf * G1_BT;
        #pragma unroll
        for (int ks = 0; ks < 4; ks++) {
            uint32_t a[4][4];
            #pragma unroll
            for (int tm = 0; tm < 4; tm++) {
                int m0 = wm * 64 + tm * 16;
                ldsm4t(a[tm], sbase + (kb * 64 + ks * 16 + ((lane >> 4) << 3) + (lane & 7)) * PITCHT
                              + (m0 + ((lane >> 3) & 1) * 8) * 2);
            }
            uint32_t b[8][2];
            #pragma unroll
            for (int tq = 0; tq < 4; tq++) {
                int n0 = wn * 64 + tq * 16;
                uint32_t r[4];
                ldsm4t(r, sB + (ks * 16 + ((lane >> 3) & 1) * 8 + (lane & 7)) * PITCHT
                          + (n0 + ((lane >> 4) << 3)) * 2);
                b[2 * tq][0] = r[0]; b[2 * tq][1] = r[1];
                b[2 * tq + 1][0] = r[2]; b[2 * tq + 1][1] = r[3];
            }
            #pragma unroll
            for (int tm = 0; tm < 4; tm++)
                #pragma unroll
                for (int tn = 0; tn < 8; tn++)
                    mma16816(acc[tm][tn], a[tm], b[tn]);
        }
        __syncthreads();

        if (kb == 3) {
            int bj = bj0 + rep;
            #pragma unroll
            for (int tm = 0; tm < 4; tm++) {
                #pragma unroll
                for (int tn = 0; tn < 8; tn++) {
                    int jd = bj * 128 + wn * 64 + tn * 8 + cp2;
                    int pcol = jd >> 5, d = jd & 31;
                    #pragma unroll
                    for (int h = 0; h < 2; h++) {
                        int ic = bi * 128 + wm * 64 + tm * 16 + r0 + h * 8;
                        __half2 hv;
                        hv.x = __float2half(acc[tm][tn][2 * h]     * invS);
                        hv.y = __float2half(acc[tm][tn][2 * h + 1] * invS);
                        size_t off = ((size_t)(ic >> 5) * NRES + pcol) * CD
                                     + (ic & 31) * 32 + d;
                        *(__half2*)(g_o + off) = hv;
                        acc[tm][tn][2 * h] = 0.f;
                        acc[tm][tn][2 * h + 1] = 0.f;
                    }
                }
            }
        }
    }
    #undef G1_LOADB
}

// -------------------------------------------------------------------------
// Kernel 3 (GEMM2): z[m,e] = O[m,:] @ W3[:,e] + b3
// M = 147456, N = 128, K = 1024, 64k-chunks, 3-stage pipeline.
// -------------------------------------------------------------------------
__global__ void __launch_bounds__(128, 2)
gemm2_mma(const float* __restrict__ b3, float* __restrict__ z) {
    extern __shared__ __align__(16) char smem[];

    const int mb = blockIdx.x;
    const int tid = threadIdx.x, lane = tid & 31, wid = tid >> 5;
    const int wm = wid & 1, wn = wid >> 1;
    const uint32_t sbase = smem_u32(smem);

    float acc[4][8][4];
    #pragma unroll
    for (int tm = 0; tm < 4; tm++)
        #pragma unroll
        for (int tn = 0; tn < 8; tn++)
            #pragma unroll
            for (int q = 0; q < 4; q++) acc[tm][tn][q] = 0.f;

    #define G2_LOAD(kb, buf) do {                                              \
        int k0 = (kb) * 64;                                                    \
        const __half* A = g_o + (size_t)(mb * 128) * CD + k0;                  \
        const __half* B = g_w3h + (size_t)k0 * CZ;                             \
        uint32_t sA = sbase + (buf) * G2_STG, sB = sA + TBA2;                  \
        _Pragma("unroll")                                                      \
        for (int it = 0; it < 8; it++) {                                       \
            int idx = tid + it * 128;                                          \
            int ra = idx >> 3, ca = idx & 7;                                   \
            cp16(sA + ra * PITCHA2 + ca * 16, A + (size_t)ra * CD + ca * 8);   \
            int rb = idx >> 4, cb = idx & 15;                                  \
            cp16(sB + rb * PITCHT + cb * 16, B + (size_t)rb * CZ + cb * 8);    \
        }                                                                      \
        asm volatile("cp.async.commit_group;" ::: "memory");                   \
    } while (0)

    G2_LOAD(0, 0);
    G2_LOAD(1, 1);
    for (int kb = 0; kb < 16; kb++) {
        int buf = kb % 3;
        if (kb + 2 < 16) {
            G2_LOAD(kb + 2, (kb + 2) % 3);
            asm volatile("cp.async.wait_group 2;" ::: "memory");
        } else if (kb + 1 < 16) {
            asm volatile("cp.async.wait_group 1;" ::: "memory");
        } else {
            asm volatile("cp.async.wait_group 0;" ::: "memory");
        }
        __syncthreads();
        uint32_t sA = sbase + buf * G2_STG, sB = sA + TBA2;
        #pragma unroll
        for (int ks = 0; ks < 4; ks++) {
            uint32_t a[4][4];
            #pragma unroll
            for (int tm = 0; tm < 4; tm++)
                ldsm4(a[tm], sA + (wm * 64 + tm * 16 + (lane & 15)) * PITCHA2
                             + ks * 32 + (lane >> 4) * 16);
            uint32_t b[8][2];
            #pragma unroll
            for (int tq = 0; tq < 4; tq++) {
                int n0 = wn * 64 + tq * 16;
                uint32_t r[4];
                ldsm4t(r, sB + (ks * 16 + ((lane >> 3) & 1) * 8 + (lane & 7)) * PITCHT
                          + (n0 + ((lane >> 4) << 3)) * 2);
                b[2 * tq][0] = r[0]; b[2 * tq][1] = r[1];
                b[2 * tq + 1][0] = r[2]; b[2 * tq + 1][1] = r[3];
            }
            #pragma unroll
            for (int tm = 0; tm < 4; tm++)
                #pragma unroll
                for (int tn = 0; tn < 8; tn++)
                    mma16816(acc[tm][tn], a[tm], b[tn]);
        }
        __syncthreads();
    }

    const int r0 = lane >> 2, cp2 = (lane & 3) * 2;
    #pragma unroll
    for (int tm = 0; tm < 4; tm++) {
        #pragma unroll
        for (int tn = 0; tn < 8; tn++) {
            int e = wn * 64 + tn * 8 + cp2;
            float be0 = __ldg(b3 + e), be1 = __ldg(b3 + e + 1);
            #pragma unroll
            for (int h = 0; h < 2; h++) {
                size_t mrow = (size_t)mb * 128 + wm * 64 + tm * 16 + r0 + h * 8;
                float2 v;
                v.x = acc[tm][tn][2 * h]     + be0;
                v.y = acc[tm][tn][2 * h + 1] + be1;
                *(float2*)(z + mrow * CZ + e) = v;
            }
        }
    }
    #undef G2_LOAD
}

// -------------------------------------------------------------------------
extern "C" void kernel_launch(void* const* d_in, const int* in_sizes, int n_in,
                              void* d_out, int out_size) {
    const float* m     = (const float*)d_in[0];
    const float* gamma = (const float*)d_in[1];
    const float* beta  = (const float*)d_in[2];
    const float* W1    = (const float*)d_in[3];
    const float* W2    = (const float*)d_in[4];
    const float* W3    = (const float*)d_in[5];
    const float* b3    = (const float*)d_in[6];
    float* z = (float*)d_out;
    (void)in_sizes; (void)n_in; (void)out_size;

    cudaFuncSetAttribute(gemm1_mma,
                         cudaFuncAttributeMaxDynamicSharedMemorySize, G1_SMEM);
    cudaFuncSetAttribute(gemm2_mma,
                         cudaFuncAttributeMaxDynamicSharedMemorySize, G2_SMEM);

    // 512 CTAs x 64 rows/sweep -> 3 sweeps of 98304 rows
    ln_proj_kernel<<<512, 128>>>(m, gamma, beta, W1, W2, W3);
    gemm1_mma<<<96 * (96 / TPC), 128, G1_SMEM>>>();   // 288 CTAs, one wave
    gemm2_mma<<<NPAIR / 128, 128, G2_SMEM>>>(b3, z);  // 1152 CTAs
}